// round 17
// baseline (speedup 1.0000x reference)
#include <cuda_runtime.h>

#define Bb 2
#define Nn 8192
#define Ff 64
#define Oo 64
#define GRID 32
#define GPB  16          // blocks per batch (barrier group size)
#define TPB 1024
#define NWARP 32
#define RPB 512          // rows per block
#define NGRP 64          // row groups (TPB/16)
#define ITERS 8          // RPB / NGRP

// Epoch-parity double-buffered accumulators: launch with epoch E uses slot E&1
// (zeroed by the previous launch / static init); lead block zeroes slot (E&1)^1
// at start for the NEXT launch.
__device__ __align__(16) float g_Sj[2][Bb];
__device__ __align__(16) float g_Pa[2][Bb * Oo];
__device__ __align__(16) float g_Qa[2][Bb * Oo];
__device__ unsigned long long g_ctr2[Bb];    // monotone per-batch barrier counters

__device__ __forceinline__ unsigned long long ctr_load_acq(const unsigned long long* p) {
    unsigned long long v;
    asm volatile("ld.acquire.gpu.global.u64 %0, [%1];" : "=l"(v) : "l"(p) : "memory");
    return v;
}
__device__ __forceinline__ unsigned long long ctr_load_cg(const unsigned long long* p) {
    unsigned long long v;
    asm volatile("ld.global.cg.u64 %0, [%1];" : "=l"(v) : "l"(p) : "memory");
    return v;
}
__device__ __forceinline__ float f_load_cg(const float* p) {
    float v;
    asm volatile("ld.global.cg.f32 %0, [%1];" : "=f"(v) : "l"(p) : "memory");
    return v;
}

__global__ void __launch_bounds__(TPB, 1) k_fused(
    const float* __restrict__ x, const float* __restrict__ adj_w,
    const float* __restrict__ adj_b, const float* __restrict__ weight,
    const float* __restrict__ bias, float* __restrict__ out)
{
    __shared__ float s_pu[NWARP * Ff];       // 8 KB (per-warp u partials)
    __shared__ float s_pv[NWARP * Ff];       // 8 KB
    __shared__ float s_red[8][2 * Ff];       // 4 KB eighth-sums
    __shared__ float s_uv[2 * Ff];           // u | v
    __shared__ float s_gp[4 * Oo];           // GEMM half partials
    __shared__ float sB[Oo];
    __shared__ float s_W[Ff * Oo];           // 16 KB
    __shared__ float s_wsum[NWARP];

    const int tid  = threadIdx.x;
    const int lane = tid & 15;               // feature quad
    const int grp  = tid >> 4;               // row group (0..63)
    const int wid  = tid >> 5;
    const int bid  = blockIdx.x;
    const int bb   = bid >> 4;               // batch (16 blocks/batch)
    const int row0 = bid * RPB;

    // Epoch parity from the monotone counter (exact multiple of 2*GPB at entry).
    const unsigned long long cv0 = ctr_load_cg(&g_ctr2[bb]);
    const int par = (int)((cv0 / (2ULL * GPB)) & 1ULL);

    const float c = adj_b[0];
    const float4 wj = reinterpret_cast<const float4*>(adj_w)[lane];
    const float4 wi = reinterpret_cast<const float4*>(adj_w)[16 + lane];

    // ---------------- Phase 1a: x first pass, wj dots only -------------------
    // x slice (128 KB) fits L1 alongside smem: later reloads are L1 hits.
    float rsj[ITERS];                        // lane-partial now, folded in 1b
    float bl = 0.0f;
    #pragma unroll
    for (int it = 0; it < ITERS; ++it) {
        const float4 xv = reinterpret_cast<const float4*>(x)[(row0 + it * NGRP + grp) * 16 + lane];
        rsj[it] = xv.x * wj.x + xv.y * wj.y + xv.z * wj.z + xv.w * wj.w;
        bl += rsj[it];
    }
    #pragma unroll
    for (int off = 16; off; off >>= 1)       // full-warp fold of block partial
        bl += __shfl_xor_sync(0xffffffffu, bl, off);
    if ((tid & 31) == 0) s_wsum[wid] = bl;

    // Stage weight + bias (off the arrival path; L2 hits).
    reinterpret_cast<float4*>(s_W)[tid] = reinterpret_cast<const float4*>(weight)[tid];
    if (tid < Oo) sB[tid] = bias[tid];

    // Lead block per batch zeroes the NEXT launch's slots.
    if ((bid & 15) == 0) {
        if (tid < Oo)            g_Pa[par ^ 1][bb * Oo + tid] = 0.0f;
        else if (tid < 2 * Oo)   g_Qa[par ^ 1][bb * Oo + tid - Oo] = 0.0f;
        else if (tid == 2 * Oo)  g_Sj[par ^ 1][bb] = 0.0f;
    }
    __syncthreads();

    // ---------------- Barrier 1 ARRIVE (warp-0 parallel fold) ----------------
    unsigned long long b1t = 0;
    if (tid < 32) {
        float s = s_wsum[tid];
        #pragma unroll
        for (int off = 16; off; off >>= 1)   // fold 32 -> 1
            s += __shfl_xor_sync(0xffffffffu, s, off);
        if (tid == 0) {
            atomicAdd(&g_Sj[par][bb], s);
            __threadfence();
            unsigned long long token = atomicAdd(&g_ctr2[bb], 1ULL);
            unsigned long long E = token / (2ULL * GPB);
            b1t = E * (2ULL * GPB) + 1ULL * GPB;
        }
    }

    // ---------------- Phase 1b: wi dots + per-row folds (hidden) -------------
    float rsi[ITERS];
    #pragma unroll
    for (int it = 0; it < ITERS; ++it) {
        const float4 xv = reinterpret_cast<const float4*>(x)[(row0 + it * NGRP + grp) * 16 + lane];
        float pi = xv.x * wi.x + xv.y * wi.y + xv.z * wi.z + xv.w * wi.w;
        #pragma unroll
        for (int off = 8; off; off >>= 1)
            pi += __shfl_xor_sync(0xffffffffu, pi, off, 16);
        rsi[it] = pi;
    }
    #pragma unroll
    for (int it = 0; it < ITERS; ++it) {
        float pj = rsj[it];
        #pragma unroll
        for (int off = 8; off; off >>= 1)
            pj += __shfl_xor_sync(0xffffffffu, pj, off, 16);
        rsj[it] = pj;
    }

    // ---------------- Barrier 1 WAIT (acquire poll) ---------------------------
    if (tid == 0) {
        while (ctr_load_acq(&g_ctr2[bb]) < b1t) __nanosleep(20);
    }
    __syncthreads();

    const float Sj = f_load_cg(&g_Sj[par][bb]);   // single broadcast L2 load

    // ---------------- Phase 2: u/v partials (x reload = L1 hits) --------------
    float4 au = make_float4(0.f, 0.f, 0.f, 0.f);
    float4 av = make_float4(0.f, 0.f, 0.f, 0.f);
    #pragma unroll
    for (int it = 0; it < ITERS; ++it) {
        const float4 xv = reinterpret_cast<const float4*>(x)[(row0 + it * NGRP + grp) * 16 + lane];
        float d  = rsqrtf(fmaxf((float)Nn * (rsi[it] + c) + Sj, 1.0f));
        float sd = rsj[it] * d;
        au.x += d  * xv.x;  au.y += d  * xv.y;
        au.z += d  * xv.z;  au.w += d  * xv.w;
        av.x += sd * xv.x;  av.y += sd * xv.y;
        av.z += sd * xv.z;  av.w += sd * xv.w;
    }
    // Fold the two 16-lane halves of each warp (same feature quads).
    au.x += __shfl_down_sync(0xffffffffu, au.x, 16);
    au.y += __shfl_down_sync(0xffffffffu, au.y, 16);
    au.z += __shfl_down_sync(0xffffffffu, au.z, 16);
    au.w += __shfl_down_sync(0xffffffffu, au.w, 16);
    av.x += __shfl_down_sync(0xffffffffu, av.x, 16);
    av.y += __shfl_down_sync(0xffffffffu, av.y, 16);
    av.z += __shfl_down_sync(0xffffffffu, av.z, 16);
    av.w += __shfl_down_sync(0xffffffffu, av.w, 16);
    if ((tid & 31) < 16) {
        reinterpret_cast<float4*>(s_pu)[wid * 16 + lane] = au;
        reinterpret_cast<float4*>(s_pv)[wid * 16 + lane] = av;
    }
    __syncthreads();

    // u/v reduce: 1024 threads, 4-deep eighths, then 128-thread combine of 8.
    {
        const int col = tid & 127;           // 0..63 -> u, 64..127 -> v
        const int h   = tid >> 7;            // eighth 0..7 (4 warp-partials each)
        const float* src = (col < 64) ? (s_pu + col) : (s_pv + (col - 64));
        float a = 0.f;
        #pragma unroll
        for (int g = 0; g < 4; ++g) a += src[(h * 4 + g) * Ff];
        s_red[h][col] = a;
    }
    __syncthreads();
    if (tid < 128) {
        float a = 0.f;
        #pragma unroll
        for (int h = 0; h < 8; ++h) a += s_red[h][tid];
        s_uv[tid] = a;
    }
    __syncthreads();

    // Micro-GEMM halves: 256 threads x 32 FMA; P,Q linear in u,v -> RED partials.
    if (tid < 256) {
        const int o   = tid & 63;
        const int sel = tid >> 6;            // 0,1 -> P halves ; 2,3 -> Q halves
        const int uvo = (sel >> 1) * 64;
        const int f0  = (sel & 1) * 32;
        float acc = 0.f;
        #pragma unroll
        for (int f = 0; f < 32; ++f)
            acc = fmaf(s_uv[uvo + f0 + f], s_W[(f0 + f) * Oo + o], acc);
        s_gp[sel * Oo + o] = acc;
    }
    __syncthreads();
    if (tid < 64) {
        atomicAdd(&g_Pa[par][bb * Oo + tid], s_gp[tid] + s_gp[Oo + tid]);
    } else if (tid < 128) {
        const int o = tid - 64;
        atomicAdd(&g_Qa[par][bb * Oo + o], s_gp[2 * Oo + o] + s_gp[3 * Oo + o]);
    }
    __syncthreads();

    // ---------------- Barrier 2 (single release fence at arrival) -------------
    if (tid == 0) {
        __threadfence();                      // publish this block's P/Q REDs
        unsigned long long token = atomicAdd(&g_ctr2[bb], 1ULL);
        unsigned long long E = token / (2ULL * GPB);
        unsigned long long t2 = E * (2ULL * GPB) + 2ULL * GPB;
        while (ctr_load_acq(&g_ctr2[bb]) < t2) __nanosleep(20);
    }
    __syncthreads();

    // ---------------- Phase 4: epilogue (d recomputed; direct P/Q loads) ------
    const int o4 = lane * 4;
    const float4 Pv = __ldcg(reinterpret_cast<const float4*>(&g_Pa[par][bb * Oo + o4]));
    const float4 Qv = __ldcg(reinterpret_cast<const float4*>(&g_Qa[par][bb * Oo + o4]));
    const float B0 = sB[o4 + 0], B1 = sB[o4 + 1], B2 = sB[o4 + 2], B3 = sB[o4 + 3];
    #pragma unroll
    for (int it = 0; it < ITERS; ++it) {
        const float a = rsi[it] + c;
        const float d = rsqrtf(fmaxf((float)Nn * a + Sj, 1.0f));
        float4 r;
        r.x = fmaxf(fmaf(d, fmaf(a, Pv.x, Qv.x), B0), 0.0f);
        r.y = fmaxf(fmaf(d, fmaf(a, Pv.y, Qv.y), B1), 0.0f);
        r.z = fmaxf(fmaf(d, fmaf(a, Pv.z, Qv.z), B2), 0.0f);
        r.w = fmaxf(fmaf(d, fmaf(a, Pv.w, Qv.w), B3), 0.0f);
        reinterpret_cast<float4*>(out)[(row0 + it * NGRP + grp) * 16 + lane] = r;
    }
}

extern "C" void kernel_launch(void* const* d_in, const int* in_sizes, int n_in,
                              void* d_out, int out_size) {
    const float* x      = (const float*)d_in[0];
    const float* adj_w  = (const float*)d_in[1];
    const float* adj_b  = (const float*)d_in[2];
    const float* weight = (const float*)d_in[3];
    const float* bias   = (const float*)d_in[4];
    float* out = (float*)d_out;

    k_fused<<<GRID, TPB>>>(x, adj_w, adj_b, weight, bias, out);
}